// round 6
// baseline (speedup 1.0000x reference)
#include <cuda_runtime.h>
#include <cuda_bf16.h>

#define BOLTZMAN 0.001987191f
#define L 64

// Coefficients, written by gle_coef_kernel, read by main kernel after PDL sync.
__device__ __align__(16) float g_cA[L];  // g_cA[s] = -mk[64-s] (s>=1), [0]=0
__device__ __align__(16) float g_cB[L];  // g_cB[s] =  h[64-s]  (s>=1), [0]=0
__device__ float g_sc[2];                // [0] = -mk[0], [1] = h[0]

// Tiny coefficient kernel: 1 block, 64 threads.
__global__ void gle_coef_kernel(const float* __restrict__ h,
                                const int* __restrict__ Traw,
                                const float* __restrict__ mass) {
    __shared__ float hs[L];
    int k = threadIdx.x;
    hs[k] = h[k];
    __syncthreads();

    float mk = 0.0f;
    #pragma unroll 8
    for (int j = 0; j + k < L; ++j) mk += hs[j] * hs[j + k];

    int ti = Traw[0];
    float T = (ti > 0 && ti < 10000000) ? (float)ti : __int_as_float(ti);
    mk *= mass[0] * BOLTZMAN * T;

    if (k == 0) {
        g_sc[0] = -mk;
        g_sc[1] = hs[0];
        g_cA[0] = 0.0f;
        g_cB[0] = 0.0f;
    } else {
        g_cA[L - k] = -mk;
        g_cB[L - k] = hs[k];
    }
}

// One thread per channel: 16 float4 loads per array along the thread's own
// 256B row, FMA vs smem-broadcast coefficients. No shuffles, no divergent
// scalar lanes, fully coalesced 1-float store. PDL secondary of coef kernel.
__global__ void __launch_bounds__(256, 4) gle_main_kernel(
    const float* __restrict__ v,
    const float* __restrict__ vlist,
    const float* __restrict__ wlist,
    const float* __restrict__ wnew,
    float* __restrict__ out,
    int nch) {
    __shared__ float4 sA[16];
    __shared__ float4 sB[16];
    __shared__ float sS[2];

    int tid = threadIdx.x;
    int c = blockIdx.x * 256 + tid;
    bool ok = (c < nch);
    int cc = ok ? c : 0;

    const float4* va = (const float4*)vlist + cc * 16;
    const float4* wa = (const float4*)wlist + cc * 16;

    // front-batch the scalar terms (coalesced across the warp)
    float vv = __ldg(&v[cc]);
    float wn = __ldg(&wnew[cc]);

    // PDL: coef kernel finishes under our launch ramp
    cudaGridDependencySynchronize();

    if (tid < 16)        sA[tid]      = __ldg(&((const float4*)g_cA)[tid]);
    else if (tid < 32)   sB[tid - 16] = __ldg(&((const float4*)g_cB)[tid - 16]);
    else if (tid == 32) { sS[0] = __ldg(&g_sc[0]); sS[1] = __ldg(&g_sc[1]); }
    __syncthreads();

    float acc0 = 0.0f, acc1 = 0.0f;
    #pragma unroll
    for (int j = 0; j < 16; j += 2) {
        float4 a0 = __ldcs(va + j);
        float4 b0 = __ldcs(wa + j);
        float4 a1 = __ldcs(va + j + 1);
        float4 b1 = __ldcs(wa + j + 1);
        float4 ca0 = sA[j],     cb0 = sB[j];
        float4 ca1 = sA[j + 1], cb1 = sB[j + 1];
        acc0 += a0.x * ca0.x + a0.y * ca0.y + a0.z * ca0.z + a0.w * ca0.w
              + b0.x * cb0.x + b0.y * cb0.y + b0.z * cb0.z + b0.w * cb0.w;
        acc1 += a1.x * ca1.x + a1.y * ca1.y + a1.z * ca1.z + a1.w * ca1.w
              + b1.x * cb1.x + b1.y * cb1.y + b1.z * cb1.z + b1.w * cb1.w;
    }

    if (ok) out[c] = acc0 + acc1 + vv * sS[0] + wn * sS[1];
}

extern "C" void kernel_launch(void* const* d_in, const int* in_sizes, int n_in,
                              void* d_out, int out_size) {
    // metadata order: v, T, dt, mass, h, v_list, w_list, w_new
    const float* v     = (const float*)d_in[0];
    const int*   Traw  = (const int*)  d_in[1];
    const float* mass  = (const float*)d_in[3];
    const float* h     = (const float*)d_in[4];
    const float* vlist = (const float*)d_in[5];
    const float* wlist = (const float*)d_in[6];
    const float* wnew  = (const float*)d_in[7];
    float* out = (float*)d_out;

    int nch = in_sizes[0];                 // 3*NATOM channels

    gle_coef_kernel<<<1, 64>>>(h, Traw, mass);

    int blocks = (nch + 255) / 256;

    cudaLaunchAttribute attrs[1];
    attrs[0].id = cudaLaunchAttributeProgrammaticStreamSerialization;
    attrs[0].val.programmaticStreamSerializationAllowed = 1;

    cudaLaunchConfig_t cfg = {};
    cfg.gridDim = dim3((unsigned)blocks, 1, 1);
    cfg.blockDim = dim3(256, 1, 1);
    cfg.dynamicSmemBytes = 0;
    cfg.stream = 0;
    cfg.attrs = attrs;
    cfg.numAttrs = 1;

    cudaLaunchKernelEx(&cfg, gle_main_kernel, v, vlist, wlist, wnew, out, nch);
}

// round 7
// speedup vs baseline: 1.7098x; 1.7098x over previous
#include <cuda_runtime.h>
#include <cuda_bf16.h>

#define BOLTZMAN 0.001987191f
#define L 64

// Coefficients, written by gle_coef_kernel, read by main kernel after PDL sync.
__device__ __align__(16) float g_cA[L];  // g_cA[s] = -mk[64-s] (s>=1), [0]=0
__device__ __align__(16) float g_cB[L];  // g_cB[s] =  h[64-s]  (s>=1), [0]=0
__device__ float g_sc[2];                // [0] = -mk[0], [1] = h[0]

// Tiny coefficient kernel: 1 block, 64 threads.
__global__ void gle_coef_kernel(const float* __restrict__ h,
                                const int* __restrict__ Traw,
                                const float* __restrict__ mass) {
    __shared__ float hs[L];
    int k = threadIdx.x;
    hs[k] = h[k];
    __syncthreads();

    float mk = 0.0f;
    #pragma unroll 8
    for (int j = 0; j + k < L; ++j) mk += hs[j] * hs[j + k];

    int ti = Traw[0];
    float T = (ti > 0 && ti < 10000000) ? (float)ti : __int_as_float(ti);
    mk *= mass[0] * BOLTZMAN * T;

    if (k == 0) {
        g_sc[0] = -mk;
        g_sc[1] = hs[0];
        g_cA[0] = 0.0f;
        g_cB[0] = 0.0f;
    } else {
        g_cA[L - k] = -mk;
        g_cB[L - k] = hs[k];
    }
}

// One-shot streaming kernel, 16 lanes per channel (one LDG.128 = 512B fully
// contiguous across 2 adjacent rows -> 4 L1 wavefronts, perfect coalescing).
// 4 channels per thread: 8 front-batched float4 LDGs (MLP=8), epilogue
// (4 interleaved shuffle chains) amortized over 2x the data vs R4.
// 512 threads/block -> 128 channels/block. PDL secondary of coef kernel.
__global__ void __launch_bounds__(512) gle_main_kernel(
    const float* __restrict__ v,
    const float* __restrict__ vlist,
    const float* __restrict__ wlist,
    const float* __restrict__ wnew,
    float* __restrict__ out,
    int nch) {
    int tid = threadIdx.x;
    int grp = tid >> 4;                 // 0..31
    int q   = tid & 15;                 // float4 index within 64-float row

    int c0 = blockIdx.x * 128 + grp;
    int c1 = c0 + 32;
    int c2 = c0 + 64;
    int c3 = c0 + 96;
    bool ok0 = (c0 < nch), ok1 = (c1 < nch), ok2 = (c2 < nch), ok3 = (c3 < nch);
    int p0 = ok0 ? c0 : 0, p1 = ok1 ? c1 : 0, p2 = ok2 ? c2 : 0, p3 = ok3 ? c3 : 0;

    const float4* vl4 = (const float4*)vlist;
    const float4* wl4 = (const float4*)wlist;

    // ---- 8 front-batched streaming loads (evict-first; touched once) ----
    const float4 a0 = __ldcs(vl4 + p0 * 16 + q);
    const float4 b0 = __ldcs(wl4 + p0 * 16 + q);
    const float4 a1 = __ldcs(vl4 + p1 * 16 + q);
    const float4 b1 = __ldcs(wl4 + p1 * 16 + q);
    const float4 a2 = __ldcs(vl4 + p2 * 16 + q);
    const float4 b2 = __ldcs(wl4 + p2 * 16 + q);
    const float4 a3 = __ldcs(vl4 + p3 * 16 + q);
    const float4 b3 = __ldcs(wl4 + p3 * 16 + q);

    // ---- scalar terms, reducer lanes only ----
    float vv0 = 0.f, wn0 = 0.f, vv1 = 0.f, wn1 = 0.f;
    float vv2 = 0.f, wn2 = 0.f, vv3 = 0.f, wn3 = 0.f;
    if (q == 0) {
        vv0 = __ldg(&v[p0]);  wn0 = __ldg(&wnew[p0]);
        vv1 = __ldg(&v[p1]);  wn1 = __ldg(&wnew[p1]);
        vv2 = __ldg(&v[p2]);  wn2 = __ldg(&wnew[p2]);
        vv3 = __ldg(&v[p3]);  wn3 = __ldg(&wnew[p3]);
    }

    // ---- PDL: coef kernel hidden under our load ramp ----
    cudaGridDependencySynchronize();

    const float4 ca = __ldg(&((const float4*)g_cA)[q]);
    const float4 cb = __ldg(&((const float4*)g_cB)[q]);
    const float s0 = __ldg(&g_sc[0]);
    const float s1 = __ldg(&g_sc[1]);

    float acc0 = a0.x * ca.x + a0.y * ca.y + a0.z * ca.z + a0.w * ca.w
               + b0.x * cb.x + b0.y * cb.y + b0.z * cb.z + b0.w * cb.w;
    float acc1 = a1.x * ca.x + a1.y * ca.y + a1.z * ca.z + a1.w * ca.w
               + b1.x * cb.x + b1.y * cb.y + b1.z * cb.z + b1.w * cb.w;
    float acc2 = a2.x * ca.x + a2.y * ca.y + a2.z * ca.z + a2.w * ca.w
               + b2.x * cb.x + b2.y * cb.y + b2.z * cb.z + b2.w * cb.w;
    float acc3 = a3.x * ca.x + a3.y * ca.y + a3.z * ca.z + a3.w * ca.w
               + b3.x * cb.x + b3.y * cb.y + b3.z * cb.z + b3.w * cb.w;

    // width-16 reductions, 4 independent chains interleaved for ILP
    acc0 += __shfl_down_sync(0xffffffffu, acc0, 8, 16);
    acc1 += __shfl_down_sync(0xffffffffu, acc1, 8, 16);
    acc2 += __shfl_down_sync(0xffffffffu, acc2, 8, 16);
    acc3 += __shfl_down_sync(0xffffffffu, acc3, 8, 16);
    acc0 += __shfl_down_sync(0xffffffffu, acc0, 4, 16);
    acc1 += __shfl_down_sync(0xffffffffu, acc1, 4, 16);
    acc2 += __shfl_down_sync(0xffffffffu, acc2, 4, 16);
    acc3 += __shfl_down_sync(0xffffffffu, acc3, 4, 16);
    acc0 += __shfl_down_sync(0xffffffffu, acc0, 2, 16);
    acc1 += __shfl_down_sync(0xffffffffu, acc1, 2, 16);
    acc2 += __shfl_down_sync(0xffffffffu, acc2, 2, 16);
    acc3 += __shfl_down_sync(0xffffffffu, acc3, 2, 16);
    acc0 += __shfl_down_sync(0xffffffffu, acc0, 1, 16);
    acc1 += __shfl_down_sync(0xffffffffu, acc1, 1, 16);
    acc2 += __shfl_down_sync(0xffffffffu, acc2, 1, 16);
    acc3 += __shfl_down_sync(0xffffffffu, acc3, 1, 16);

    if (q == 0) {
        if (ok0) out[c0] = acc0 + vv0 * s0 + wn0 * s1;
        if (ok1) out[c1] = acc1 + vv1 * s0 + wn1 * s1;
        if (ok2) out[c2] = acc2 + vv2 * s0 + wn2 * s1;
        if (ok3) out[c3] = acc3 + vv3 * s0 + wn3 * s1;
    }
}

extern "C" void kernel_launch(void* const* d_in, const int* in_sizes, int n_in,
                              void* d_out, int out_size) {
    // metadata order: v, T, dt, mass, h, v_list, w_list, w_new
    const float* v     = (const float*)d_in[0];
    const int*   Traw  = (const int*)  d_in[1];
    const float* mass  = (const float*)d_in[3];
    const float* h     = (const float*)d_in[4];
    const float* vlist = (const float*)d_in[5];
    const float* wlist = (const float*)d_in[6];
    const float* wnew  = (const float*)d_in[7];
    float* out = (float*)d_out;

    int nch = in_sizes[0];                 // 3*NATOM channels

    gle_coef_kernel<<<1, 64>>>(h, Traw, mass);

    int blocks = (nch + 127) / 128;

    cudaLaunchAttribute attrs[1];
    attrs[0].id = cudaLaunchAttributeProgrammaticStreamSerialization;
    attrs[0].val.programmaticStreamSerializationAllowed = 1;

    cudaLaunchConfig_t cfg = {};
    cfg.gridDim = dim3((unsigned)blocks, 1, 1);
    cfg.blockDim = dim3(512, 1, 1);
    cfg.dynamicSmemBytes = 0;
    cfg.stream = 0;
    cfg.attrs = attrs;
    cfg.numAttrs = 1;

    cudaLaunchKernelEx(&cfg, gle_main_kernel, v, vlist, wlist, wnew, out, nch);
}

// round 10
// speedup vs baseline: 1.7887x; 1.0462x over previous
#include <cuda_runtime.h>
#include <cuda_bf16.h>

#define BOLTZMAN 0.001987191f
#define L 64

// Coefficients, written by gle_coef_kernel, read by main kernel (after PDL
// sync when PDL is active; plain stream order otherwise).
__device__ __align__(16) float g_cA[L];  // g_cA[s] = -mk[64-s] (s>=1), [0]=0
__device__ __align__(16) float g_cB[L];  // g_cB[s] =  h[64-s]  (s>=1), [0]=0
__device__ float g_sc[2];                // [0] = -mk[0], [1] = h[0]

// Tiny coefficient kernel: 1 block, 64 threads.
__global__ void gle_coef_kernel(const float* __restrict__ h,
                                const int* __restrict__ Traw,
                                const float* __restrict__ mass) {
    __shared__ float hs[L];
    int k = threadIdx.x;
    hs[k] = h[k];
    __syncthreads();

    float mk = 0.0f;
    #pragma unroll 8
    for (int j = 0; j + k < L; ++j) mk += hs[j] * hs[j + k];

    int ti = Traw[0];
    float T = (ti > 0 && ti < 10000000) ? (float)ti : __int_as_float(ti);
    mk *= mass[0] * BOLTZMAN * T;

    if (k == 0) {
        g_sc[0] = -mk;
        g_sc[1] = hs[0];
        g_cA[0] = 0.0f;
        g_cB[0] = 0.0f;
    } else {
        g_cA[L - k] = -mk;
        g_cB[L - k] = hs[k];
    }
}

// R4 structure (512 thr, 2 channels/thread, 32 regs, 4 blocks/SM) with:
//  - adjacent channel pairing (c1 = c0+1): warp's streaming loads span ~1KB
//    contiguous per array; outputs adjacent -> single float2 store per group
//  - broadcast (non-divergent) scalar-term loads
__global__ void __launch_bounds__(512) gle_main_kernel(
    const float* __restrict__ v,
    const float* __restrict__ vlist,
    const float* __restrict__ wlist,
    const float* __restrict__ wnew,
    float* __restrict__ out,
    int nch) {
    int tid = threadIdx.x;
    int grp = tid >> 4;                 // 0..31
    int q   = tid & 15;                 // float4 index within 64-float row

    int c0 = blockIdx.x * 64 + grp * 2; // even channel
    int c1 = c0 + 1;                    // odd channel (adjacent)
    bool ok0 = (c0 < nch), ok1 = (c1 < nch);
    int p0 = ok0 ? c0 : 0, p1 = ok1 ? c1 : 0;

    const float4* vl4 = (const float4*)vlist;
    const float4* wl4 = (const float4*)wlist;

    // ---- front-batched streaming loads (evict-first, touched once) ----
    const float4 a0 = __ldcs(vl4 + p0 * 16 + q);
    const float4 b0 = __ldcs(wl4 + p0 * 16 + q);
    const float4 a1 = __ldcs(vl4 + p1 * 16 + q);
    const float4 b1 = __ldcs(wl4 + p1 * 16 + q);

    // ---- scalar terms: broadcast loads, no divergence (same addr per 16-group) ----
    const float vv0 = __ldg(&v[p0]);
    const float wn0 = __ldg(&wnew[p0]);
    const float vv1 = __ldg(&v[p1]);
    const float wn1 = __ldg(&wnew[p1]);

    // ---- PDL sync: coef kernel hidden under the load ramp above.
    //      No-op if launched without the PDL attribute. ----
    cudaGridDependencySynchronize();

    const float4 ca = __ldg(&((const float4*)g_cA)[q]);
    const float4 cb = __ldg(&((const float4*)g_cB)[q]);
    const float s0 = __ldg(&g_sc[0]);
    const float s1 = __ldg(&g_sc[1]);

    float acc0 = a0.x * ca.x + a0.y * ca.y + a0.z * ca.z + a0.w * ca.w
               + b0.x * cb.x + b0.y * cb.y + b0.z * cb.z + b0.w * cb.w;
    float acc1 = a1.x * ca.x + a1.y * ca.y + a1.z * ca.z + a1.w * ca.w
               + b1.x * cb.x + b1.y * cb.y + b1.z * cb.z + b1.w * cb.w;

    // width-16 reduction, two chains interleaved
    acc0 += __shfl_down_sync(0xffffffffu, acc0, 8, 16);
    acc1 += __shfl_down_sync(0xffffffffu, acc1, 8, 16);
    acc0 += __shfl_down_sync(0xffffffffu, acc0, 4, 16);
    acc1 += __shfl_down_sync(0xffffffffu, acc1, 4, 16);
    acc0 += __shfl_down_sync(0xffffffffu, acc0, 2, 16);
    acc1 += __shfl_down_sync(0xffffffffu, acc1, 2, 16);
    acc0 += __shfl_down_sync(0xffffffffu, acc0, 1, 16);
    acc1 += __shfl_down_sync(0xffffffffu, acc1, 1, 16);

    if (q == 0) {
        float r0 = acc0 + vv0 * s0 + wn0 * s1;
        float r1 = acc1 + vv1 * s0 + wn1 * s1;
        if (ok1) {
            // both valid, adjacent, c0 even -> 8B-aligned single store
            float2 r = make_float2(r0, r1);
            *reinterpret_cast<float2*>(out + c0) = r;
        } else if (ok0) {
            out[c0] = r0;
        }
    }
}

extern "C" void kernel_launch(void* const* d_in, const int* in_sizes, int n_in,
                              void* d_out, int out_size) {
    // metadata order: v, T, dt, mass, h, v_list, w_list, w_new
    const float* v     = (const float*)d_in[0];
    const int*   Traw  = (const int*)  d_in[1];
    const float* mass  = (const float*)d_in[3];
    const float* h     = (const float*)d_in[4];
    const float* vlist = (const float*)d_in[5];
    const float* wlist = (const float*)d_in[6];
    const float* wnew  = (const float*)d_in[7];
    float* out = (float*)d_out;

    int nch = in_sizes[0];                 // 3*NATOM channels

    gle_coef_kernel<<<1, 64>>>(h, Traw, mass);

    int blocks = (nch + 63) / 64;

    // Preferred path: PDL launch so the main kernel's load ramp hides the
    // coef kernel + launch gap.
    cudaLaunchAttribute attrs[1];
    attrs[0].id = cudaLaunchAttributeProgrammaticStreamSerialization;
    attrs[0].val.programmaticStreamSerializationAllowed = 1;

    cudaLaunchConfig_t cfg = {};
    cfg.gridDim = dim3((unsigned)blocks, 1, 1);
    cfg.blockDim = dim3(512, 1, 1);
    cfg.dynamicSmemBytes = 0;
    cfg.stream = 0;
    cfg.attrs = attrs;
    cfg.numAttrs = 1;

    cudaError_t e = cudaLaunchKernelEx(&cfg, gle_main_kernel,
                                       v, vlist, wlist, wnew, out, nch);
    if (e != cudaSuccess) {
        // Clear sticky error and fall back to a plain serialized launch.
        (void)cudaGetLastError();
        gle_main_kernel<<<blocks, 512>>>(v, vlist, wlist, wnew, out, nch);
    }
}